// round 1
// baseline (speedup 1.0000x reference)
#include <cuda_runtime.h>
#include <cstdint>

// ---------------- problem constants ----------------
#define LL   2
#define TT   512
#define BB   128
#define FF   4
#define HH   256
#define CLSZ 8      // CTAs per cluster
#define NCL  16     // clusters
#define NTHR 128    // threads per CTA

// ---------------- smem layout (floats) ----------------
#define OFF_U    0          // [256 h][128 cols]            32768
#define OFF_HB   32768      // [2][256 h][8 b]               4096
#define OFF_PRE  36864      // [8 b][128 cols]               1024
#define OFF_WX   37888      // [128 cols][4 f]                512
#define OFF_WB   38400      // [128 cols]                     128
#define OFF_FCW  38528      // [32 k][4 f]                    128
#define OFF_FCB  38656      // [4]                              4
#define OFF_YP   38660      // [2][8 src][4 f]                 64
#define SMEM_FLOATS 38724
#define SMEM_BYTES (SMEM_FLOATS * 4)

// layer-1 output scratch: [T][B][F]
__device__ float g_y1[TT * BB * FF];

// ---------------- helpers ----------------
__device__ __forceinline__ uint32_t smem_u32(const void* p) {
    uint32_t a;
    asm("{ .reg .u64 t; cvta.to.shared.u64 t, %1; cvt.u32.u64 %0, t; }"
        : "=r"(a) : "l"(p));
    return a;
}
__device__ __forceinline__ void cluster_sync() {
    asm volatile("barrier.cluster.arrive.aligned;" ::: "memory");
    asm volatile("barrier.cluster.wait.aligned;" ::: "memory");
}
__device__ __forceinline__ unsigned long long pack2(float a, float b) {
    unsigned long long r;
    asm("mov.b64 %0, {%1, %2};" : "=l"(r) : "f"(a), "f"(b));
    return r;
}
__device__ __forceinline__ float2 unpack2(unsigned long long v) {
    float2 r;
    asm("mov.b64 {%0, %1}, %2;" : "=f"(r.x), "=f"(r.y) : "l"(v));
    return r;
}
__device__ __forceinline__ unsigned long long ffma2(unsigned long long a,
                                                    unsigned long long b,
                                                    unsigned long long c) {
    unsigned long long d;
    asm("fma.rn.f32x2 %0, %1, %2, %3;" : "=l"(d) : "l"(a), "l"(b), "l"(c));
    return d;
}
__device__ __forceinline__ float sigf(float x) {
    return 1.0f / (1.0f + __expf(-x));
}

// quaternion layout: sel = hb ^ cb ; negative-sign mask over idx = cb*4+hb
#define QNEG_MASK 0x284E

__global__ void __launch_bounds__(NTHR) __cluster_dims__(CLSZ, 1, 1)
qlstm_kernel(const float* __restrict__ x,
             const float* __restrict__ Wxr, const float* __restrict__ Wxi,
             const float* __restrict__ Wxj, const float* __restrict__ Wxk,
             const float* __restrict__ Wxb,
             const float* __restrict__ Ur,  const float* __restrict__ Ui,
             const float* __restrict__ Uj,  const float* __restrict__ Uk,
             const float* __restrict__ fcw, const float* __restrict__ fcb,
             float* __restrict__ out)
{
    extern __shared__ float sm[];
    float* sU   = sm + OFF_U;
    float* sHB  = sm + OFF_HB;
    float* sPre = sm + OFF_PRE;
    float* sWx  = sm + OFF_WX;
    float* sWb  = sm + OFF_WB;
    float* sFW  = sm + OFF_FCW;
    float* sFB  = sm + OFF_FCB;
    float* sYP  = sm + OFF_YP;

    const int tid  = threadIdx.x;
    const int lane = tid & 31;
    const int warp = tid >> 5;
    const int r    = blockIdx.x & 7;   // cluster rank
    const int cid  = blockIdx.x >> 3;  // cluster id
    const int col  = tid;              // GEMM: column 0..127 (= g*32 + k_local)
    const int k    = lane;             // activation: k_local
    const int b0   = warp * 2;         // activation: batch pair
    const int b1   = b0 + 1;
    const uint32_t sbase = smem_u32(sm);

    for (int l = 0; l < LL; l++) {
        __syncthreads();  // protect smem tables from previous phase readers

        // ---- gather U slice: sU[h*128 + g*32 + kl] = sign * comp[n][m] ----
        for (int idx = tid; idx < 4 * 256 * 32; idx += NTHR) {
            int g   = idx >> 13;
            int rem = idx & 8191;
            int h   = rem >> 5;
            int kl  = rem & 31;
            int kg  = r * 32 + kl;
            int hb  = h >> 6, n = h & 63;
            int cb  = kg >> 6, m = kg & 63;
            int sel = hb ^ cb;
            float sgn = ((QNEG_MASK >> (cb * 4 + hb)) & 1) ? -1.0f : 1.0f;
            const float* cp = (sel == 0) ? Ur : (sel == 1) ? Ui : (sel == 2) ? Uj : Uk;
            sU[h * 128 + g * 32 + kl] =
                sgn * __ldg(&cp[((l * 4 + g) * 64 + n) * 64 + m]);
        }
        // ---- gather Wx slice: sWx[(g*32+kl)*4 + f] ----
        for (int idx = tid; idx < 512; idx += NTHR) {
            int g  = idx >> 7;
            int f  = (idx >> 5) & 3;
            int kl = idx & 31;
            int kg = r * 32 + kl;
            int cb = kg >> 6, m = kg & 63;
            int sel = f ^ cb;
            float sgn = ((QNEG_MASK >> (cb * 4 + f)) & 1) ? -1.0f : 1.0f;
            const float* cp = (sel == 0) ? Wxr : (sel == 1) ? Wxi : (sel == 2) ? Wxj : Wxk;
            sWx[(g * 32 + kl) * 4 + f] = sgn * __ldg(&cp[(l * 4 + g) * 64 + m]);
        }
        // ---- gather biases / fco weights ----
        for (int idx = tid; idx < 128; idx += NTHR) {
            int g = idx >> 5, kl = idx & 31;
            sWb[idx] = Wxb[(l * 4 + g) * 256 + r * 32 + kl];
            int kf = idx >> 2, f = idx & 3;
            sFW[idx] = fcw[(l * 256 + r * 32 + kf) * 4 + f];
        }
        if (tid < 4) sFB[tid] = fcb[l * 4 + tid];
        // ---- zero both h buffers ----
        for (int i = tid; i < 2 * 256 * 8; i += NTHR) sHB[i] = 0.0f;
        float2 creg = make_float2(0.0f, 0.0f);

        cluster_sync();

        const float4* xp = (const float4*)((l == 0) ? x : g_y1);

        for (int t = 0; t < TT; t++) {
            const int cur = t & 1;
            const int nxt = cur ^ 1;
            const float* hbc = sHB + cur * 2048;

            // ---- init acc = wb + x_t @ Wx (per col, 8 batches) ----
            float4 wxc = *(const float4*)&sWx[col * 4];
            float  wbc = sWb[col];
            float acc[8];
#pragma unroll
            for (int j = 0; j < 8; j++) {
                int xi = (l == 0) ? ((cid * 8 + j) * TT + t)
                                  : (t * BB + cid * 8 + j);
                float4 xv = __ldg(&xp[xi]);
                acc[j] = wbc + xv.x * wxc.x + xv.y * wxc.y
                             + xv.z * wxc.z + xv.w * wxc.w;
            }
            unsigned long long A0 = pack2(acc[0], acc[1]);
            unsigned long long A1 = pack2(acc[2], acc[3]);
            unsigned long long A2 = pack2(acc[4], acc[5]);
            unsigned long long A3 = pack2(acc[6], acc[7]);

            // ---- main GEMM: pre[col][b] += sum_h h[b][h] * U[h][col] ----
#pragma unroll 8
            for (int h = 0; h < HH; h++) {
                float u = sU[h * 128 + col];
                unsigned long long uu = pack2(u, u);
                ulonglong2 p01 = *(const ulonglong2*)(hbc + h * 8);
                ulonglong2 p23 = *(const ulonglong2*)(hbc + h * 8 + 4);
                A0 = ffma2(p01.x, uu, A0);
                A1 = ffma2(p01.y, uu, A1);
                A2 = ffma2(p23.x, uu, A2);
                A3 = ffma2(p23.y, uu, A3);
            }

            // ---- scatter pre to smem [b][col] ----
            {
                float2 v;
                v = unpack2(A0); sPre[0 * 128 + col] = v.x; sPre[1 * 128 + col] = v.y;
                v = unpack2(A1); sPre[2 * 128 + col] = v.x; sPre[3 * 128 + col] = v.y;
                v = unpack2(A2); sPre[4 * 128 + col] = v.x; sPre[5 * 128 + col] = v.y;
                v = unpack2(A3); sPre[6 * 128 + col] = v.x; sPre[7 * 128 + col] = v.y;
            }
            __syncthreads();

            // ---- activations + cell update (thread owns (k, b0) and (k, b1)) ----
            float hn0, hn1;
            {
                const float* pb = sPre + b0 * 128 + k;
                float ft = sigf(pb[0]);
                float it = sigf(pb[32]);
                float ot = sigf(pb[64]);
                float ct = tanhf(pb[96]);
                float c  = it * ct + ft * creg.x;
                creg.x = c;
                hn0 = ot * tanhf(c);
            }
            {
                const float* pb = sPre + b1 * 128 + k;
                float ft = sigf(pb[0]);
                float it = sigf(pb[32]);
                float ot = sigf(pb[64]);
                float ct = tanhf(pb[96]);
                float c  = it * ct + ft * creg.y;
                creg.y = c;
                hn1 = ot * tanhf(c);
            }

            // ---- broadcast h slice to all 8 CTAs (DSMEM) ----
            {
                unsigned long long hh = pack2(hn0, hn1);
                uint32_t haddr = sbase + (OFF_HB + nxt * 2048 + (r * 32 + k) * 8 + b0) * 4;
#pragma unroll
                for (int j = 0; j < 8; j++) {
                    uint32_t ra;
                    asm("mapa.shared::cluster.u32 %0, %1, %2;" : "=r"(ra) : "r"(haddr), "r"(j));
                    asm volatile("st.shared::cluster.b64 [%0], %1;" :: "r"(ra), "l"(hh) : "memory");
                }
            }

            // ---- fco partials: warp-reduce over k ----
            float4 fw = *(const float4*)&sFW[k * 4];
            float v00 = hn0 * fw.x, v01 = hn0 * fw.y, v02 = hn0 * fw.z, v03 = hn0 * fw.w;
            float v10 = hn1 * fw.x, v11 = hn1 * fw.y, v12 = hn1 * fw.z, v13 = hn1 * fw.w;
#pragma unroll
            for (int m = 16; m >= 1; m >>= 1) {
                v00 += __shfl_xor_sync(0xffffffffu, v00, m);
                v01 += __shfl_xor_sync(0xffffffffu, v01, m);
                v02 += __shfl_xor_sync(0xffffffffu, v02, m);
                v03 += __shfl_xor_sync(0xffffffffu, v03, m);
                v10 += __shfl_xor_sync(0xffffffffu, v10, m);
                v11 += __shfl_xor_sync(0xffffffffu, v11, m);
                v12 += __shfl_xor_sync(0xffffffffu, v12, m);
                v13 += __shfl_xor_sync(0xffffffffu, v13, m);
            }
            const int ybuf = t & 1;
            if (lane == 0) {
                uint32_t ya = sbase + (OFF_YP + ybuf * 32 + r * 4) * 4;
                unsigned long long q0 = pack2(v00, v01);
                unsigned long long q1 = pack2(v02, v03);
                uint32_t ra;
                asm("mapa.shared::cluster.u32 %0, %1, %2;" : "=r"(ra) : "r"(ya), "r"(b0));
                asm volatile("st.shared::cluster.b64 [%0], %1;" :: "r"(ra), "l"(q0) : "memory");
                asm volatile("st.shared::cluster.b64 [%0], %1;" :: "r"(ra + 8), "l"(q1) : "memory");
                q0 = pack2(v10, v11);
                q1 = pack2(v12, v13);
                asm("mapa.shared::cluster.u32 %0, %1, %2;" : "=r"(ra) : "r"(ya), "r"(b1));
                asm volatile("st.shared::cluster.b64 [%0], %1;" :: "r"(ra), "l"(q0) : "memory");
                asm volatile("st.shared::cluster.b64 [%0], %1;" :: "r"(ra + 8), "l"(q1) : "memory");
            }

            cluster_sync();

            // ---- finalize y for this CTA's batch (bmine = cid*8 + r) ----
            if (tid < 32) {
                float v = sYP[ybuf * 32 + tid];
                v += __shfl_xor_sync(0xffffffffu, v, 4);
                v += __shfl_xor_sync(0xffffffffu, v, 8);
                v += __shfl_xor_sync(0xffffffffu, v, 16);
                v += sFB[tid & 3];
                float nn = v * v;
                nn += __shfl_xor_sync(0xffffffffu, nn, 1);
                nn += __shfl_xor_sync(0xffffffffu, nn, 2);
                float dn = fmaxf(sqrtf(nn), 1e-12f);
                float yv = v / dn;
                if (tid < 4) {
                    if (l == 0) {
                        g_y1[(t * BB + cid * 8 + r) * 4 + tid] = yv;
                    } else if (t == TT - 1) {
                        out[(cid * 8 + r) * 4 + tid] = yv;
                    }
                }
            }
        } // t
    } // l
}

extern "C" void kernel_launch(void* const* d_in, const int* in_sizes, int n_in,
                              void* d_out, int out_size)
{
    (void)in_sizes; (void)n_in; (void)out_size;
    cudaFuncSetAttribute(qlstm_kernel,
                         cudaFuncAttributeMaxDynamicSharedMemorySize, SMEM_BYTES);
    qlstm_kernel<<<NCL * CLSZ, NTHR, SMEM_BYTES>>>(
        (const float*)d_in[0],
        (const float*)d_in[1], (const float*)d_in[2],
        (const float*)d_in[3], (const float*)d_in[4],
        (const float*)d_in[5],
        (const float*)d_in[6], (const float*)d_in[7],
        (const float*)d_in[8], (const float*)d_in[9],
        (const float*)d_in[10], (const float*)d_in[11],
        (float*)d_out);
}

// round 2
// speedup vs baseline: 1.6722x; 1.6722x over previous
#include <cuda_runtime.h>
#include <cstdint>

// ---------------- problem constants ----------------
#define LL   2
#define TT   512
#define BB   128
#define HH   256
#define CLSZ 8      // CTAs per cluster
#define NCL  16     // clusters
#define NTHR 512    // threads per CTA (16 warps, 4/SMSP)

// ---------------- smem layout (float indices) ----------------
#define OFF_U    0          // [128 cols][260 pad h]        33280
#define OFF_HB   33280      // [2][256 h][8 b]               4096
#define OFF_PAR  37376      // [3 kq][128 col][8 b]          3072
#define OFF_PRE  40448      // [8 b][128 col]                1024
#define OFF_WX   41472      // [128 col][4 f]                 512
#define OFF_WB   41984      // [128 col]                      128
#define OFF_FCW  42112      // [32 k][4 f]                    128
#define OFF_FCB  42240      // [4]                              4
#define OFF_YP   42248      // [2][8 src][4 f]                 64
#define SMEM_FLOATS 42312
#define SMEM_BYTES (SMEM_FLOATS * 4)

// layer-1 output scratch: [T][B][F]
__device__ float g_y1[TT * BB * 4];

typedef unsigned long long ull;

// ---------------- helpers ----------------
__device__ __forceinline__ uint32_t smem_u32(const void* p) {
    uint32_t a;
    asm("{ .reg .u64 t; cvta.to.shared.u64 t, %1; cvt.u32.u64 %0, t; }"
        : "=r"(a) : "l"(p));
    return a;
}
__device__ __forceinline__ void cluster_sync() {
    asm volatile("barrier.cluster.arrive.aligned;" ::: "memory");
    asm volatile("barrier.cluster.wait.aligned;" ::: "memory");
}
__device__ __forceinline__ ull pack2(float a, float b) {
    ull r;
    asm("mov.b64 %0, {%1, %2};" : "=l"(r) : "f"(a), "f"(b));
    return r;
}
__device__ __forceinline__ float2 unpack2(ull v) {
    float2 r;
    asm("mov.b64 {%0, %1}, %2;" : "=f"(r.x), "=f"(r.y) : "l"(v));
    return r;
}
__device__ __forceinline__ ull ffma2(ull a, ull b, ull c) {
    ull d;
    asm("fma.rn.f32x2 %0, %1, %2, %3;" : "=l"(d) : "l"(a), "l"(b), "l"(c));
    return d;
}
__device__ __forceinline__ ull add2(ull a, ull b) {
    ull d;
    asm("add.rn.f32x2 %0, %1, %2;" : "=l"(d) : "l"(a), "l"(b));
    return d;
}
// fast sigmoid / tanh via MUFU ex2 + rcp (err ~1e-6, budget is 1e-3)
__device__ __forceinline__ float fsig(float x) {
    float e, r;
    asm("ex2.approx.f32 %0, %1;" : "=f"(e) : "f"(x * -1.4426950408889634f));
    asm("rcp.approx.f32 %0, %1;" : "=f"(r) : "f"(1.0f + e));
    return r;
}
__device__ __forceinline__ float ftanh(float x) {
    float e, r;
    asm("ex2.approx.f32 %0, %1;" : "=f"(e) : "f"(x * -2.8853900817779268f));
    asm("rcp.approx.f32 %0, %1;" : "=f"(r) : "f"(1.0f + e));
    return __fmaf_rn(2.0f, r, -1.0f);
}

// quaternion sign mask over idx = cb*4 + hb
#define QNEG_MASK 0x284E

__global__ void __launch_bounds__(NTHR, 1) __cluster_dims__(CLSZ, 1, 1)
qlstm_kernel(const float* __restrict__ x,
             const float* __restrict__ Wxr, const float* __restrict__ Wxi,
             const float* __restrict__ Wxj, const float* __restrict__ Wxk,
             const float* __restrict__ Wxb,
             const float* __restrict__ Ur,  const float* __restrict__ Ui,
             const float* __restrict__ Uj,  const float* __restrict__ Uk,
             const float* __restrict__ fcw, const float* __restrict__ fcb,
             float* __restrict__ out)
{
    extern __shared__ float sm[];
    float* sU   = sm + OFF_U;
    float* sHB  = sm + OFF_HB;
    float* sPar = sm + OFF_PAR;
    float* sPre = sm + OFF_PRE;
    float* sWx  = sm + OFF_WX;
    float* sWb  = sm + OFF_WB;
    float* sFW  = sm + OFF_FCW;
    float* sFB  = sm + OFF_FCB;
    float* sYP  = sm + OFF_YP;

    const int tid  = threadIdx.x;
    const int lane = tid & 31;
    const int col  = tid & 127;        // GEMM column (= g*32 + k_local)
    const int kq   = tid >> 7;         // split-K quarter 0..3
    const int r    = blockIdx.x & 7;   // cluster rank
    const int cid  = blockIdx.x >> 3;  // cluster id
    const int k    = lane;             // activation: k_local (tid<128)
    const int aw   = tid >> 5;         // warp id (activation warps 0..3)
    const int b0   = aw * 2;
    const int b1   = b0 + 1;
    const uint32_t sbase = smem_u32(sm);

    float2 creg = make_float2(0.0f, 0.0f);

    for (int l = 0; l < LL; l++) {
        __syncthreads();  // previous-phase readers done with smem

        // ---- gather U slice transposed+padded: sU[col*260 + h] ----
        for (int idx = tid; idx < 4 * 256 * 32; idx += NTHR) {
            int g   = idx >> 13;
            int rem = idx & 8191;
            int h   = rem >> 5;
            int kl  = rem & 31;
            int kg  = r * 32 + kl;
            int hb  = h >> 6, n = h & 63;
            int cb  = kg >> 6, m = kg & 63;
            int sel = hb ^ cb;
            float sgn = ((QNEG_MASK >> (cb * 4 + hb)) & 1) ? -1.0f : 1.0f;
            const float* cp = (sel == 0) ? Ur : (sel == 1) ? Ui : (sel == 2) ? Uj : Uk;
            sU[(g * 32 + kl) * 260 + h] =
                sgn * __ldg(&cp[((l * 4 + g) * 64 + n) * 64 + m]);
        }
        // ---- Wx slice: sWx[(g*32+kl)*4 + f] ----
        for (int idx = tid; idx < 512; idx += NTHR) {
            int g  = idx >> 7;
            int f  = (idx >> 5) & 3;
            int kl = idx & 31;
            int kg = r * 32 + kl;
            int cb = kg >> 6, m = kg & 63;
            int sel = f ^ cb;
            float sgn = ((QNEG_MASK >> (cb * 4 + f)) & 1) ? -1.0f : 1.0f;
            const float* cp = (sel == 0) ? Wxr : (sel == 1) ? Wxi : (sel == 2) ? Wxj : Wxk;
            sWx[(g * 32 + kl) * 4 + f] = sgn * __ldg(&cp[(l * 4 + g) * 64 + m]);
        }
        // ---- biases / fco weights ----
        for (int idx = tid; idx < 128; idx += NTHR) {
            int g = idx >> 5, kl = idx & 31;
            sWb[idx] = Wxb[(l * 4 + g) * 256 + r * 32 + kl];
            int kf = idx >> 2, f = idx & 3;
            sFW[idx] = fcw[(l * 256 + r * 32 + kf) * 4 + f];
        }
        if (tid < 4) sFB[tid] = fcb[l * 4 + tid];
        // ---- zero both h buffers ----
        for (int i = tid; i < 2 * 256 * 8; i += NTHR) sHB[i] = 0.0f;
        creg = make_float2(0.0f, 0.0f);

        cluster_sync();

        const float4* xp   = (const float4*)((l == 0) ? x : g_y1);
        const int     xstr = (l == 0) ? 1 : BB;
        int xbase[1];
        // per-thread x bases handled inline below

        for (int t = 0; t < TT; t++) {
            const int cur = t & 1;
            const int nxt = cur ^ 1;
            const float* hbc = sHB + cur * 2048 + kq * 512;   // kq*64 h * 8 b
            const float* up  = sU + col * 260 + kq * 64;

            // ---- acc init: kq==0 adds bias + x_t @ Wx; others start 0 ----
            ull A0, A1, A2, A3;
            if (kq == 0) {
                float4 wxc = *(const float4*)&sWx[col * 4];
                float  wbc = sWb[col];
                float acc[8];
#pragma unroll
                for (int j = 0; j < 8; j++) {
                    int xi = (l == 0) ? ((cid * 8 + j) * TT + t)
                                      : (t * BB + cid * 8 + j);
                    float4 xv = __ldg(&xp[xi]);
                    acc[j] = wbc + xv.x * wxc.x + xv.y * wxc.y
                                 + xv.z * wxc.z + xv.w * wxc.w;
                }
                A0 = pack2(acc[0], acc[1]);
                A1 = pack2(acc[2], acc[3]);
                A2 = pack2(acc[4], acc[5]);
                A3 = pack2(acc[6], acc[7]);
            } else {
                A0 = A1 = A2 = A3 = 0ull;
            }

            // ---- GEMM quarter: 64 h, 8 batches ----
#pragma unroll
            for (int hh = 0; hh < 64; hh += 4) {
                float4 u4 = *(const float4*)(up + hh);
                const float* hp = hbc + hh * 8;
                {
                    ull uu = pack2(u4.x, u4.x);
                    ulonglong2 a = *(const ulonglong2*)(hp);
                    ulonglong2 b = *(const ulonglong2*)(hp + 4);
                    A0 = ffma2(a.x, uu, A0); A1 = ffma2(a.y, uu, A1);
                    A2 = ffma2(b.x, uu, A2); A3 = ffma2(b.y, uu, A3);
                }
                {
                    ull uu = pack2(u4.y, u4.y);
                    ulonglong2 a = *(const ulonglong2*)(hp + 8);
                    ulonglong2 b = *(const ulonglong2*)(hp + 12);
                    A0 = ffma2(a.x, uu, A0); A1 = ffma2(a.y, uu, A1);
                    A2 = ffma2(b.x, uu, A2); A3 = ffma2(b.y, uu, A3);
                }
                {
                    ull uu = pack2(u4.z, u4.z);
                    ulonglong2 a = *(const ulonglong2*)(hp + 16);
                    ulonglong2 b = *(const ulonglong2*)(hp + 20);
                    A0 = ffma2(a.x, uu, A0); A1 = ffma2(a.y, uu, A1);
                    A2 = ffma2(b.x, uu, A2); A3 = ffma2(b.y, uu, A3);
                }
                {
                    ull uu = pack2(u4.w, u4.w);
                    ulonglong2 a = *(const ulonglong2*)(hp + 24);
                    ulonglong2 b = *(const ulonglong2*)(hp + 28);
                    A0 = ffma2(a.x, uu, A0); A1 = ffma2(a.y, uu, A1);
                    A2 = ffma2(b.x, uu, A2); A3 = ffma2(b.y, uu, A3);
                }
            }

            // ---- write split-K partials (kq 1..3) ----
            if (kq != 0) {
                float* pp = sPar + (kq - 1) * 1024 + col * 8;
                ((ulonglong2*)pp)[0] = make_ulonglong2(A0, A1);
                ((ulonglong2*)(pp + 4))[0] = make_ulonglong2(A2, A3);
            }
            __syncthreads();

            // ---- combine + scatter to sPre[b][col] (kq==0 threads) ----
            if (tid < 128) {
#pragma unroll
                for (int q = 0; q < 3; q++) {
                    const float* pp = sPar + q * 1024 + col * 8;
                    ulonglong2 a = *(const ulonglong2*)(pp);
                    ulonglong2 b = *(const ulonglong2*)(pp + 4);
                    A0 = add2(A0, a.x); A1 = add2(A1, a.y);
                    A2 = add2(A2, b.x); A3 = add2(A3, b.y);
                }
                float2 v;
                v = unpack2(A0); sPre[0 * 128 + col] = v.x; sPre[1 * 128 + col] = v.y;
                v = unpack2(A1); sPre[2 * 128 + col] = v.x; sPre[3 * 128 + col] = v.y;
                v = unpack2(A2); sPre[4 * 128 + col] = v.x; sPre[5 * 128 + col] = v.y;
                v = unpack2(A3); sPre[6 * 128 + col] = v.x; sPre[7 * 128 + col] = v.y;
            }
            __syncthreads();

            // ---- activations + cell update + broadcast + fco (tid<128) ----
            if (tid < 128) {
                float hn0, hn1;
                {
                    const float* pb = sPre + b0 * 128 + k;
                    float ft = fsig(pb[0]);
                    float it = fsig(pb[32]);
                    float ot = fsig(pb[64]);
                    float ct = ftanh(pb[96]);
                    float c  = it * ct + ft * creg.x;
                    creg.x = c;
                    hn0 = ot * ftanh(c);
                }
                {
                    const float* pb = sPre + b1 * 128 + k;
                    float ft = fsig(pb[0]);
                    float it = fsig(pb[32]);
                    float ot = fsig(pb[64]);
                    float ct = ftanh(pb[96]);
                    float c  = it * ct + ft * creg.y;
                    creg.y = c;
                    hn1 = ot * ftanh(c);
                }

                // broadcast h slice to all 8 CTAs (DSMEM)
                {
                    ull hh = pack2(hn0, hn1);
                    uint32_t haddr = sbase + (OFF_HB + nxt * 2048 + (r * 32 + k) * 8 + b0) * 4;
#pragma unroll
                    for (int j = 0; j < 8; j++) {
                        uint32_t ra;
                        asm("mapa.shared::cluster.u32 %0, %1, %2;" : "=r"(ra) : "r"(haddr), "r"(j));
                        asm volatile("st.shared::cluster.b64 [%0], %1;" :: "r"(ra), "l"(hh) : "memory");
                    }
                }

                // fco partials: warp-reduce over k
                float4 fw = *(const float4*)&sFW[k * 4];
                float v00 = hn0 * fw.x, v01 = hn0 * fw.y, v02 = hn0 * fw.z, v03 = hn0 * fw.w;
                float v10 = hn1 * fw.x, v11 = hn1 * fw.y, v12 = hn1 * fw.z, v13 = hn1 * fw.w;
#pragma unroll
                for (int m = 16; m >= 1; m >>= 1) {
                    v00 += __shfl_xor_sync(0xffffffffu, v00, m);
                    v01 += __shfl_xor_sync(0xffffffffu, v01, m);
                    v02 += __shfl_xor_sync(0xffffffffu, v02, m);
                    v03 += __shfl_xor_sync(0xffffffffu, v03, m);
                    v10 += __shfl_xor_sync(0xffffffffu, v10, m);
                    v11 += __shfl_xor_sync(0xffffffffu, v11, m);
                    v12 += __shfl_xor_sync(0xffffffffu, v12, m);
                    v13 += __shfl_xor_sync(0xffffffffu, v13, m);
                }
                if (lane == 0) {
                    uint32_t ya = sbase + (OFF_YP + (t & 1) * 32 + r * 4) * 4;
                    ull q0 = pack2(v00, v01);
                    ull q1 = pack2(v02, v03);
                    uint32_t ra;
                    asm("mapa.shared::cluster.u32 %0, %1, %2;" : "=r"(ra) : "r"(ya), "r"(b0));
                    asm volatile("st.shared::cluster.b64 [%0], %1;" :: "r"(ra), "l"(q0) : "memory");
                    asm volatile("st.shared::cluster.b64 [%0], %1;" :: "r"(ra + 8), "l"(q1) : "memory");
                    q0 = pack2(v10, v11);
                    q1 = pack2(v12, v13);
                    asm("mapa.shared::cluster.u32 %0, %1, %2;" : "=r"(ra) : "r"(ya), "r"(b1));
                    asm volatile("st.shared::cluster.b64 [%0], %1;" :: "r"(ra), "l"(q0) : "memory");
                    asm volatile("st.shared::cluster.b64 [%0], %1;" :: "r"(ra + 8), "l"(q1) : "memory");
                }
            }

            cluster_sync();

            // ---- finalize y for this CTA's batch (cid*8 + r) ----
            if (tid < 32) {
                float v = sYP[(t & 1) * 32 + tid];
                v += __shfl_xor_sync(0xffffffffu, v, 4);
                v += __shfl_xor_sync(0xffffffffu, v, 8);
                v += __shfl_xor_sync(0xffffffffu, v, 16);
                v += sFB[tid & 3];
                float nn = v * v;
                nn += __shfl_xor_sync(0xffffffffu, nn, 1);
                nn += __shfl_xor_sync(0xffffffffu, nn, 2);
                float dn = fmaxf(sqrtf(nn), 1e-12f);
                float yv = v / dn;
                if (tid < 4) {
                    if (l == 0) {
                        g_y1[(t * BB + cid * 8 + r) * 4 + tid] = yv;
                    } else if (t == TT - 1) {
                        out[(cid * 8 + r) * 4 + tid] = yv;
                    }
                }
            }
        } // t
    } // l
}

extern "C" void kernel_launch(void* const* d_in, const int* in_sizes, int n_in,
                              void* d_out, int out_size)
{
    (void)in_sizes; (void)n_in; (void)out_size;
    cudaFuncSetAttribute(qlstm_kernel,
                         cudaFuncAttributeMaxDynamicSharedMemorySize, SMEM_BYTES);
    qlstm_kernel<<<NCL * CLSZ, NTHR, SMEM_BYTES>>>(
        (const float*)d_in[0],
        (const float*)d_in[1], (const float*)d_in[2],
        (const float*)d_in[3], (const float*)d_in[4],
        (const float*)d_in[5],
        (const float*)d_in[6], (const float*)d_in[7],
        (const float*)d_in[8], (const float*)d_in[9],
        (const float*)d_in[10], (const float*)d_in[11],
        (float*)d_out);
}